// round 6
// baseline (speedup 1.0000x reference)
#include <cuda_runtime.h>
#include <cstdint>

#define DIN   512
#define DOUT  4096
#define CAP   96          // max stored nonzeros per column

#define RB    32          // batch rows per GEMM CTA (1 row per lane)
#define WARPS 16
#define CPW   64          // columns per warp
#define XP    33          // x-tile pitch in floats (33%32=1 -> conflict-free LDS.32)
#define OSP   9           // out-staging pitch

// ---------------- device scratch (static: allocation-free) ----------------
// g_list entries: {byte offset idx*XP*4, fp32 bits of W*mask}, zero-padded to
// a multiple of 8 entries (exact: adding 0.0f is fp32-exact). Region beyond
// the padded count is never written -> stays 0 from static init.
__device__ __align__(16) int2  g_list[DOUT * CAP];
__device__            int      g_nnz[DOUT];    // true nnz (clamped to CAP)
__device__            int      g_cnt[DOUT];    // ceil(min(nnz,64)/8) blocks
__device__ __align__(16) float g_boost[DOUT];

// ---------------- kernel 1: compact sparse lists + boost ----------------
__global__ void k_prep(const float* __restrict__ W, const float* __restrict__ M,
                       const float* __restrict__ duty, const int* __restrict__ kptr) {
    int gt = blockIdx.x * blockDim.x + threadIdx.x;
    if (gt < DOUT) {
        float target = (float)(*kptr) / (float)DOUT;
        g_boost[gt] = expf(0.5f * (target - duty[gt]));
    }
    int j    = blockIdx.x * (blockDim.x >> 5) + (threadIdx.x >> 5);
    int lane = threadIdx.x & 31;
    if (j >= DOUT) return;
    const float* Wr = W + (size_t)j * DIN;
    const float* Mr = M + (size_t)j * DIN;
    int base = 0;
    for (int c = 0; c < DIN / 32; ++c) {
        int i = c * 32 + lane;
        float w = Wr[i] * Mr[i];                 // mask is exactly 0.0 or 1.0
        bool nz = (w != 0.0f);
        unsigned bal = __ballot_sync(0xffffffffu, nz);
        int pos = base + __popc(bal & ((1u << lane) - 1u));
        if (nz && pos < CAP)
            g_list[j * CAP + pos] = make_int2(i * XP * 4, __float_as_int(w));
        base += __popc(bal);
    }
    int n      = (base < 64) ? base : 64;
    int blocks = (n + 7) >> 3;
    int npad   = blocks * 8;
    if (n + lane < npad)                         // exact zero padding
        g_list[j * CAP + n + lane] = make_int2(0, 0);
    if (lane == 0) {
        g_cnt[j] = blocks;
        g_nnz[j] = (base < CAP) ? base : CAP;
    }
}

// ---------------- kernel 2: sparse gather GEMM (fp32 exact) ----------------
// RB=32, 1 row/lane -> 108KB smem -> 2 CTAs/SM (8 warps/SMSP) for latency
// hiding. Inner loop: 8-entry blocks, 4x LDS.128 broadcast + 8x LDS.32
// gather + 8 FFMA. 2-slot smem ring for lists, counts+bias pre-staged.
__global__ void __launch_bounds__(32 * WARPS, 2)
k_gemm(const float* __restrict__ x, const float* __restrict__ bias,
       float* __restrict__ yout, int gybase) {
    extern __shared__ float sm[];
    float* xs   = sm;                              // [DIN][XP]
    float* os   = xs + DIN * XP;                   // [WARPS][RB][OSP]
    int2*  ring = (int2*)(os + WARPS * RB * OSP);  // [WARPS][2][64]
    int*   scnt = (int*)(ring + WARPS * 2 * 64);   // [1024]
    float* sbia = (float*)(scnt + WARPS * CPW);    // [1024]

    int tid  = threadIdx.x;
    int w    = tid >> 5;
    int lane = tid & 31;
    int rowbase = blockIdx.x * RB;
    int colbase = (gybase + blockIdx.y) * (WARPS * CPW);

    const float4* x4 = (const float4*)(x + (size_t)rowbase * DIN);
    for (int t = tid; t < RB * (DIN / 4); t += blockDim.x) {
        int r  = t >> 7;
        int i4 = t & 127;
        float4 v = x4[(size_t)r * (DIN / 4) + i4];
        int ib = i4 * 4;
        xs[(ib + 0) * XP + r] = v.x;
        xs[(ib + 1) * XP + r] = v.y;
        xs[(ib + 2) * XP + r] = v.z;
        xs[(ib + 3) * XP + r] = v.w;
    }
    for (int t = tid; t < WARPS * CPW; t += blockDim.x) {
        scnt[t] = g_cnt[colbase + t];
        sbia[t] = __ldg(&bias[colbase + t]);
    }
    __syncthreads();

    float* osw   = os + w * (RB * OSP);
    int    jwarp = colbase + w * CPW;
    int    jloc0 = w * CPW;
    const char* xbase = (const char*)xs + lane * 4;   // this lane's row slot
    int2*  rng   = ring + w * 2 * 64;

    // prologue: stage col 0 into slot 0; reg-hold col 1
    const int2* L = &g_list[(size_t)jwarp * CAP];
    rng[lane] = __ldg(L + lane); rng[32 + lane] = __ldg(L + 32 + lane);
    L = &g_list[(size_t)(jwarp + 1) * CAP];
    int2 rA = __ldg(L + lane), rB = __ldg(L + 32 + lane);
    __syncwarp();

    for (int ci = 0; ci < CPW; ++ci) {
        if (ci + 1 < CPW) {                        // stage ci+1, prefetch ci+2
            int2* sb = rng + ((ci + 1) & 1) * 64;
            sb[lane] = rA; sb[32 + lane] = rB;
            if (ci + 2 < CPW) {
                L = &g_list[(size_t)(jwarp + ci + 2) * CAP];
                rA = __ldg(L + lane); rB = __ldg(L + 32 + lane);
            }
        }

        int nb = scnt[jloc0 + ci];
        const int4* sb4 = (const int4*)(rng + (ci & 1) * 64);
        float acc = 0.f;
        #pragma unroll 1
        for (int t = 0; t < nb; ++t) {
            int4 q0 = sb4[t * 4 + 0];
            int4 q1 = sb4[t * 4 + 1];
            int4 q2 = sb4[t * 4 + 2];
            int4 q3 = sb4[t * 4 + 3];
            float a0 = *(const float*)(xbase + q0.x);
            float a1 = *(const float*)(xbase + q0.z);
            float a2 = *(const float*)(xbase + q1.x);
            float a3 = *(const float*)(xbase + q1.z);
            float a4 = *(const float*)(xbase + q2.x);
            float a5 = *(const float*)(xbase + q2.z);
            float a6 = *(const float*)(xbase + q3.x);
            float a7 = *(const float*)(xbase + q3.z);
            acc = fmaf(a0, __int_as_float(q0.y), acc);
            acc = fmaf(a1, __int_as_float(q0.w), acc);
            acc = fmaf(a2, __int_as_float(q1.y), acc);
            acc = fmaf(a3, __int_as_float(q1.w), acc);
            acc = fmaf(a4, __int_as_float(q2.y), acc);
            acc = fmaf(a5, __int_as_float(q2.w), acc);
            acc = fmaf(a6, __int_as_float(q3.y), acc);
            acc = fmaf(a7, __int_as_float(q3.w), acc);
        }
        if (nb == 8) {                              // ~never: nnz>64 fallback
            int j = jwarp + ci;
            int nn = __ldg(&g_nnz[j]);
            for (int e = 64; e < nn; ++e) {
                int2 pe = __ldg(&g_list[(size_t)j * CAP + e]);
                acc = fmaf(*(const float*)(xbase + pe.x),
                           __int_as_float(pe.y), acc);
            }
        }
        int cc = ci & 7;
        osw[lane * OSP + cc] = acc + sbia[jloc0 + ci];

        if (cc == 7) {
            __syncwarp();
            int j0 = jwarp + (ci & ~7);
            #pragma unroll
            for (int q = 0; q < 2; ++q) {          // 32 rows x 8 cols
                int chunk = q * 32 + lane;         // 0..63 float4s
                int row   = chunk >> 1;
                int c0    = (chunk & 1) * 4;
                float4 v;
                v.x = osw[row * OSP + c0 + 0];
                v.y = osw[row * OSP + c0 + 1];
                v.z = osw[row * OSP + c0 + 2];
                v.w = osw[row * OSP + c0 + 3];
                *(float4*)&yout[(size_t)(rowbase + row) * DOUT + j0 + c0] = v;
            }
        }
        __syncwarp();   // ring-slot handoff
    }
}

// ---------------- kernel 3: register-resident radix select ----------------
__global__ void __launch_bounds__(256)
k_select(float* __restrict__ y, const int* __restrict__ kptr) {
    __shared__ unsigned hist[256];
    __shared__ unsigned s_prefix;
    __shared__ int      s_kk;

    int tid = threadIdx.x;
    size_t rowoff = (size_t)blockIdx.x * DOUT;
    const float4* y4 = (const float4*)(y + rowoff);
    const float4* b4 = (const float4*)g_boost;

    float    vreg[16];
    unsigned kreg[16];
    #pragma unroll
    for (int q = 0; q < 4; ++q) {
        int t = tid + 256 * q;
        float4 v  = y4[t];
        float4 bo = b4[t];
        float bv[4] = { v.x * bo.x, v.y * bo.y, v.z * bo.z, v.w * bo.w };
        vreg[q * 4 + 0] = v.x; vreg[q * 4 + 1] = v.y;
        vreg[q * 4 + 2] = v.z; vreg[q * 4 + 3] = v.w;
        #pragma unroll
        for (int e = 0; e < 4; ++e) {
            unsigned u = __float_as_uint(bv[e]);
            kreg[q * 4 + e] = (u & 0x80000000u) ? ~u : (u | 0x80000000u);
        }
    }
    if (tid == 0) { s_prefix = 0u; s_kk = *kptr; }
    __syncthreads();

    for (int pass = 0; pass < 4; ++pass) {
        int shift = 24 - 8 * pass;
        hist[tid] = 0u;
        __syncthreads();
        unsigned prefix = s_prefix;
        int kk = s_kk;
        unsigned hi_mask = (pass == 0) ? 0u : (0xFFFFFFFFu << (shift + 8));
        #pragma unroll
        for (int q = 0; q < 16; ++q) {
            unsigned key = kreg[q];
            bool act = ((key & hi_mask) == prefix);
            unsigned bal = __ballot_sync(0xffffffffu, act);
            if (act) {
                int bin = (key >> shift) & 255;
                unsigned mm = __match_any_sync(bal, bin);
                int leader = __ffs(mm) - 1;
                if ((tid & 31) == leader) atomicAdd(&hist[bin], __popc(mm));
            }
        }
        __syncthreads();
        if (tid == 0) {
            int acc = 0, b = 255;
            for (; b >= 0; --b) {
                int nb = acc + (int)hist[b];
                if (nb >= kk) break;
                acc = nb;
            }
            s_prefix = prefix | ((unsigned)b << shift);
            s_kk = kk - acc;
        }
        __syncthreads();
    }

    unsigned thr = s_prefix;
    float4* yo4 = (float4*)(y + rowoff);
    #pragma unroll
    for (int q = 0; q < 4; ++q) {
        int t = tid + 256 * q;
        float4 v;
        v.x = (kreg[q * 4 + 0] >= thr) ? vreg[q * 4 + 0] : 0.f;
        v.y = (kreg[q * 4 + 1] >= thr) ? vreg[q * 4 + 1] : 0.f;
        v.z = (kreg[q * 4 + 2] >= thr) ? vreg[q * 4 + 2] : 0.f;
        v.w = (kreg[q * 4 + 3] >= thr) ? vreg[q * 4 + 3] : 0.f;
        yo4[t] = v;
    }
}

// ---------------- launch ----------------
extern "C" void kernel_launch(void* const* d_in, const int* in_sizes, int n_in,
                              void* d_out, int out_size) {
    const float* x    = (const float*)d_in[0];
    const float* W    = (const float*)d_in[1];
    const float* b    = (const float*)d_in[2];
    const float* m    = (const float*)d_in[3];
    const float* duty = (const float*)d_in[4];
    const int*   k    = (const int*)d_in[5];
    float* out = (float*)d_out;

    int B = in_sizes[0] / DIN;   // 16384

    k_prep<<<DOUT / 8, 256>>>(W, m, duty, k);

    const int smem_bytes = (DIN * XP + WARPS * RB * OSP) * (int)sizeof(float)
                         + WARPS * 2 * 64 * (int)sizeof(int2)
                         + WARPS * CPW * (int)(sizeof(int) + sizeof(float)); // 108KB
    cudaFuncSetAttribute(k_gemm, cudaFuncAttributeMaxDynamicSharedMemorySize, smem_bytes);
    dim3 grid(B / RB, 2);   // two launches of (512, 2) for ncu attribution
    k_gemm<<<grid, 32 * WARPS, smem_bytes>>>(x, b, out, 0);
    k_gemm<<<grid, 32 * WARPS, smem_bytes>>>(x, b, out, 2);

    k_select<<<B, 256>>>(out, k);
}

// round 9
// speedup vs baseline: 1.5433x; 1.5433x over previous
#include <cuda_runtime.h>
#include <cstdint>

#define DIN   512
#define DOUT  4096
#define CAP   96          // max stored nonzeros per column

#define RB    64          // batch rows per GEMM CTA (2 rows per lane)
#define WARPS 16
#define CPW   64          // columns per warp
#define XPITCH 66         // x-tile pitch (even -> aligned float2, conflict-free)
#define OSP   9           // out-staging pitch

// ---------------- device scratch (static: allocation-free) ----------------
// g_list entries: {byte offset idx*XPITCH*4, fp32 bits of W*mask}, padded to
// even count with exact {0, 0.0f} (adding 0.0 is fp32-exact).
__device__ __align__(16) int2  g_list[DOUT * CAP];
__device__            int      g_nnz[DOUT];
__device__ __align__(16) float g_boost[DOUT];

// ---------------- kernel 1: compact sparse lists + boost ----------------
__global__ void k_prep(const float* __restrict__ W, const float* __restrict__ M,
                       const float* __restrict__ duty, const int* __restrict__ kptr) {
    int gt = blockIdx.x * blockDim.x + threadIdx.x;
    if (gt < DOUT) {
        float target = (float)(*kptr) / (float)DOUT;
        g_boost[gt] = expf(0.5f * (target - duty[gt]));
    }
    int j    = blockIdx.x * (blockDim.x >> 5) + (threadIdx.x >> 5);
    int lane = threadIdx.x & 31;
    if (j >= DOUT) return;
    const float* Wr = W + (size_t)j * DIN;
    const float* Mr = M + (size_t)j * DIN;
    int base = 0;
    for (int c = 0; c < DIN / 32; ++c) {
        int i = c * 32 + lane;
        float w = Wr[i] * Mr[i];                 // mask is exactly 0.0 or 1.0
        bool nz = (w != 0.0f);
        unsigned bal = __ballot_sync(0xffffffffu, nz);
        int pos = base + __popc(bal & ((1u << lane) - 1u));
        if (nz && pos < CAP)
            g_list[j * CAP + pos] = make_int2(i * XPITCH * 4, __float_as_int(w));
        base += __popc(bal);
    }
    if (lane == 0) {
        int n = (base < CAP) ? base : CAP;
        if ((n & 1) && n < CAP) g_list[j * CAP + n] = make_int2(0, 0); // exact pad
        g_nnz[j] = n;
    }
}

// ---------------- kernel 2: sparse gather GEMM (fp32 exact, R4 config) ------
__global__ void __launch_bounds__(32 * WARPS, 1)
k_gemm(const float* __restrict__ x, const float* __restrict__ bias,
       float* __restrict__ yout) {
    extern __shared__ float sm[];
    float* xs  = sm;                       // [DIN][XPITCH] transposed x tile
    float* os  = sm + DIN * XPITCH;        // [WARPS][RB][OSP] out staging
    int4*  stg = (int4*)(os + WARPS * RB * OSP); // [WARPS][2][32] entry pairs
    int tid  = threadIdx.x;
    int w    = tid >> 5;
    int lane = tid & 31;
    int rowbase = blockIdx.x * RB;

    const float4* x4 = (const float4*)(x + (size_t)rowbase * DIN);
    for (int t = tid; t < RB * (DIN / 4); t += blockDim.x) {
        int r  = t >> 7;
        int i4 = t & 127;
        float4 v = x4[(size_t)r * (DIN / 4) + i4];
        int ib = i4 * 4;
        xs[(ib + 0) * XPITCH + r] = v.x;
        xs[(ib + 1) * XPITCH + r] = v.y;
        xs[(ib + 2) * XPITCH + r] = v.z;
        xs[(ib + 3) * XPITCH + r] = v.w;
    }
    __syncthreads();

    float* osw  = os + w * (RB * OSP);
    int jwarp   = blockIdx.y * (WARPS * CPW) + w * CPW;
    const char* xbase = (const char*)xs + lane * 8;
    int2* stgw = (int2*)(stg + w * 64);

    const int2* L;
    L = &g_list[(size_t)jwarp * CAP];
    int2 rA = __ldg(L + lane), rB = __ldg(L + 32 + lane);
    int n_cur = __ldg(&g_nnz[jwarp]);
    stgw[lane] = rA; stgw[32 + lane] = rB;
    L = &g_list[(size_t)(jwarp + 1) * CAP];
    rA = __ldg(L + lane); rB = __ldg(L + 32 + lane);
    int n_nxt = __ldg(&g_nnz[jwarp + 1]);
    __syncwarp();

    for (int ci = 0; ci < CPW; ++ci) {
        int j = jwarp + ci;
        if (ci + 1 < CPW) {
            int2* sb = stgw + ((ci + 1) & 1) * 64;
            sb[lane] = rA; sb[32 + lane] = rB;
        }
        int n_pf = 0;
        if (ci + 2 < CPW) {
            L = &g_list[(size_t)(jwarp + ci + 2) * CAP];
            rA = __ldg(L + lane); rB = __ldg(L + 32 + lane);
            n_pf = __ldg(&g_nnz[jwarp + ci + 2]);
        }

        const int4* sb4 = (const int4*)(stgw + (ci & 1) * 64);
        int nc = (n_cur < 64) ? n_cur : 64;
        int npairs = (nc + 1) >> 1;
        float acc0 = 0.f, acc1 = 0.f;
        #pragma unroll 4
        for (int p = 0; p < npairs; ++p) {
            int4 q = sb4[p];
            float2 xv0 = *(const float2*)(xbase + q.x);
            float2 xv1 = *(const float2*)(xbase + q.z);
            float v0 = __int_as_float(q.y);
            float v1 = __int_as_float(q.w);
            acc0 = fmaf(xv0.x, v0, acc0);
            acc1 = fmaf(xv0.y, v0, acc1);
            acc0 = fmaf(xv1.x, v1, acc0);
            acc1 = fmaf(xv1.y, v1, acc1);
        }
        if (n_cur > 64) {
            for (int e = 64; e < n_cur; ++e) {
                int2 pe = __ldg(&g_list[(size_t)j * CAP + e]);
                float v = __int_as_float(pe.y);
                float2 xv = *(const float2*)(xbase + pe.x);
                acc0 = fmaf(xv.x, v, acc0);
                acc1 = fmaf(xv.y, v, acc1);
            }
        }
        float bj = __ldg(&bias[j]);
        int cc = ci & 7;
        osw[(2 * lane)     * OSP + cc] = acc0 + bj;
        osw[(2 * lane + 1) * OSP + cc] = acc1 + bj;

        n_cur = n_nxt; n_nxt = n_pf;

        if (cc == 7) {
            __syncwarp();
            int j0 = jwarp + (ci & ~7);
            #pragma unroll
            for (int q = 0; q < 4; ++q) {
                int chunk = q * 32 + lane;
                int row   = chunk >> 1;
                int c0    = (chunk & 1) * 4;
                float4 v;
                v.x = osw[row * OSP + c0 + 0];
                v.y = osw[row * OSP + c0 + 1];
                v.z = osw[row * OSP + c0 + 2];
                v.w = osw[row * OSP + c0 + 3];
                *(float4*)&yout[(size_t)(rowbase + row) * DOUT + j0 + c0] = v;
            }
        }
        __syncwarp();
    }
}

// ---------------- kernel 3: radix select, parallel scan, per-warp hists -----
__global__ void __launch_bounds__(256)
k_select(float* __restrict__ y, const int* __restrict__ kptr) {
    __shared__ unsigned whist[8 * 256];   // per-warp histograms
    __shared__ unsigned ssum[256];        // suffix sums
    __shared__ unsigned warptot[8];
    __shared__ unsigned s_prefix;
    __shared__ int      s_kk;

    int tid  = threadIdx.x;
    int w    = tid >> 5;
    int lane = tid & 31;
    size_t rowoff = (size_t)blockIdx.x * DOUT;
    const float4* y4 = (const float4*)(y + rowoff);
    const float4* b4 = (const float4*)g_boost;

    float    vreg[16];
    unsigned kreg[16];
    #pragma unroll
    for (int q = 0; q < 4; ++q) {
        int t = tid + 256 * q;
        float4 v  = y4[t];
        float4 bo = b4[t];
        float bv[4] = { v.x * bo.x, v.y * bo.y, v.z * bo.z, v.w * bo.w };
        vreg[q * 4 + 0] = v.x; vreg[q * 4 + 1] = v.y;
        vreg[q * 4 + 2] = v.z; vreg[q * 4 + 3] = v.w;
        #pragma unroll
        for (int e = 0; e < 4; ++e) {
            unsigned u = __float_as_uint(bv[e]);
            kreg[q * 4 + e] = (u & 0x80000000u) ? ~u : (u | 0x80000000u);
        }
    }
    #pragma unroll
    for (int h = 0; h < 8; ++h) whist[h * 256 + tid] = 0u;
    if (tid == 0) { s_prefix = 0u; s_kk = *kptr; }
    unsigned act = 0xffffu;               // 16-bit active-element mask
    __syncthreads();

    for (int pass = 0; pass < 4; ++pass) {
        int shift = 24 - 8 * pass;
        int kk = s_kk;
        // histogram active elements into this warp's private hist
        unsigned m = act;
        while (m) {
            int q = __ffs(m) - 1; m &= m - 1;
            atomicAdd(&whist[w * 256 + ((kreg[q] >> shift) & 255)], 1u);
        }
        __syncthreads();
        // reduce 8 warp hists for bin = tid
        unsigned h = 0;
        #pragma unroll
        for (int ww = 0; ww < 8; ++ww) h += whist[ww * 256 + tid];
        // descending inclusive scan within warp segment (bins tid..segEnd)
        unsigned v = h;
        #pragma unroll
        for (int off = 1; off < 32; off <<= 1) {
            unsigned o = __shfl_down_sync(0xffffffffu, v, off);
            if (lane + off < 32) v += o;
        }
        if (lane == 0) warptot[w] = v;
        __syncthreads();
        unsigned above = 0;
        #pragma unroll
        for (int ww = 0; ww < 8; ++ww) if (ww > w) above += warptot[ww];
        unsigned S = v + above;           // S[tid] = sum of h over bins >= tid
        ssum[tid] = S;
        #pragma unroll
        for (int hh = 0; hh < 8; ++hh) whist[hh * 256 + tid] = 0u; // re-zero
        __syncthreads();
        unsigned Snext = (tid == 255) ? 0u : ssum[tid + 1];
        if (S >= (unsigned)kk && Snext < (unsigned)kk) {   // exactly one thread
            s_prefix |= ((unsigned)tid) << shift;
            s_kk = kk - (int)Snext;
        }
        __syncthreads();
        // refine active set to the boundary bin
        unsigned pb = (s_prefix >> shift) & 255u;
        unsigned m2 = act; act = 0u;
        while (m2) {
            int q = __ffs(m2) - 1; m2 &= m2 - 1;
            if (((kreg[q] >> shift) & 255u) == pb) act |= 1u << q;
        }
    }

    unsigned thr = s_prefix;              // exact key of kth largest
    float4* yo4 = (float4*)(y + rowoff);
    #pragma unroll
    for (int q = 0; q < 4; ++q) {
        int t = tid + 256 * q;
        float4 v;
        v.x = (kreg[q * 4 + 0] >= thr) ? vreg[q * 4 + 0] : 0.f;
        v.y = (kreg[q * 4 + 1] >= thr) ? vreg[q * 4 + 1] : 0.f;
        v.z = (kreg[q * 4 + 2] >= thr) ? vreg[q * 4 + 2] : 0.f;
        v.w = (kreg[q * 4 + 3] >= thr) ? vreg[q * 4 + 3] : 0.f;
        yo4[t] = v;
    }
}

// ---------------- launch ----------------
extern "C" void kernel_launch(void* const* d_in, const int* in_sizes, int n_in,
                              void* d_out, int out_size) {
    const float* x    = (const float*)d_in[0];
    const float* W    = (const float*)d_in[1];
    const float* b    = (const float*)d_in[2];
    const float* m    = (const float*)d_in[3];
    const float* duty = (const float*)d_in[4];
    const int*   k    = (const int*)d_in[5];
    float* out = (float*)d_out;

    int B = in_sizes[0] / DIN;   // 16384

    k_prep<<<DOUT / 8, 256>>>(W, m, duty, k);

    const int smem_bytes = (DIN * XPITCH + WARPS * RB * OSP) * (int)sizeof(float)
                         + WARPS * 2 * 32 * (int)sizeof(int4);   // 172KB + 16KB
    cudaFuncSetAttribute(k_gemm, cudaFuncAttributeMaxDynamicSharedMemorySize, smem_bytes);
    dim3 grid(B / RB, DOUT / (WARPS * CPW));   // (256, 4)
    k_gemm<<<grid, 32 * WARPS, smem_bytes>>>(x, b, out);

    k_select<<<B, 256>>>(out, k);
}